// round 16
// baseline (speedup 1.0000x reference)
#include <cuda_runtime.h>
#include <cuda_fp16.h>
#include <cstdint>

#define N_MAX   100000
#define E_MAX   1600000
#define IN_DIM  128
#define SCAN_B  1024
#define NB_MAX  128   // ceil(N_MAX/SCAN_B)=98 <= 128

// static scratch (no allocation allowed)
__device__ float  g_h[(size_t)N_MAX * 128];    // fp16 h_norm per layer
__device__ float  g_agg[(size_t)N_MAX * 128];  // layer-1 aggregate (fp32)
__device__ float  g_dinv[N_MAX];
__device__ int    g_deg[N_MAX];
__device__ int    g_offs[N_MAX + 1];
__device__ int    g_cursor[N_MAX];
__device__ int    g_csr_src[E_MAX];
__device__ int    g_blocksums[NB_MAX];
// fragment-ordered fp16 weights: layer1 8ks*16nt*32lanes uint2, layer2 8ks*8nt*32 uint2
__device__ uint2  g_fw[8 * 16 * 32 + 8 * 8 * 32];

// ---------------------------------------------------------------------------
// init: zero deg + build fragment-ordered fp16 W for both layers.
// ---------------------------------------------------------------------------
__global__ void init_kernel(const float* __restrict__ W1, const float* __restrict__ W2,
                            uint2* __restrict__ fw, int* __restrict__ deg, int N) {
    int i = blockIdx.x * blockDim.x + threadIdx.x;
    if (i < N) deg[i] = 0;
    const int C1 = 8 * 16 * 32;
    const int C2 = 8 * 8 * 32;
    if (i < C1) {
        int ks = i / (16 * 32), rem = i % (16 * 32);
        int nt = rem / 32, lane = rem % 32;
        int g = lane >> 2, r = lane & 3;
        int n = nt * 8 + g, k = ks * 16 + r * 2;
        __half2 b0 = __floats2half2_rn(W1[k * 128 + n],       W1[(k + 1) * 128 + n]);
        __half2 b1 = __floats2half2_rn(W1[(k + 8) * 128 + n], W1[(k + 9) * 128 + n]);
        uint2 u; u.x = *(uint32_t*)&b0; u.y = *(uint32_t*)&b1;
        fw[i] = u;
    } else if (i < C1 + C2) {
        int j = i - C1;
        int ks = j / (8 * 32), rem = j % (8 * 32);
        int nt = rem / 32, lane = rem % 32;
        int g = lane >> 2, r = lane & 3;
        int n = nt * 8 + g, k = ks * 16 + r * 2;
        __half2 b0 = __floats2half2_rn(W2[k * 64 + n],       W2[(k + 1) * 64 + n]);
        __half2 b1 = __floats2half2_rn(W2[(k + 8) * 64 + n], W2[(k + 9) * 64 + n]);
        uint2 u; u.x = *(uint32_t*)&b0; u.y = *(uint32_t*)&b1;
        fw[C1 + j] = u;
    }
}

// ---------------------------------------------------------------------------
// CSR build
// ---------------------------------------------------------------------------
__global__ void deg_kernel(const int* __restrict__ dst, int* __restrict__ deg, int E) {
    int e = blockIdx.x * blockDim.x + threadIdx.x;
    if (e < E) atomicAdd(&deg[dst[e]], 1);
}

__global__ void deg4_kernel(const int* __restrict__ dst, int* __restrict__ deg, int E) {
    int e4 = (blockIdx.x * blockDim.x + threadIdx.x) * 4;
    if (e4 >= E) return;
    int4 d = *(const int4*)&dst[e4];
    atomicAdd(&deg[d.x], 1);
    atomicAdd(&deg[d.y], 1);
    atomicAdd(&deg[d.z], 1);
    atomicAdd(&deg[d.w], 1);
}

__global__ void scan_block_kernel(const int* __restrict__ deg, int* __restrict__ offs,
                                  int* __restrict__ blocksums, float* __restrict__ dinv, int N) {
    __shared__ int sh[SCAN_B];
    int i = blockIdx.x * SCAN_B + threadIdx.x;
    int v = (i < N) ? deg[i] : 0;
    if (i < N) dinv[i] = rsqrtf((float)(v + 1));
    sh[threadIdx.x] = v; __syncthreads();
    for (int off = 1; off < SCAN_B; off <<= 1) {
        int t = (threadIdx.x >= off) ? sh[threadIdx.x - off] : 0;
        __syncthreads();
        sh[threadIdx.x] += t;
        __syncthreads();
    }
    if (i < N) offs[i] = sh[threadIdx.x] - v;
    if (threadIdx.x == SCAN_B - 1) blocksums[blockIdx.x] = sh[threadIdx.x];
}

__global__ void scan_add_kernel(int* __restrict__ offs, const int* __restrict__ blocksums,
                                int* __restrict__ cursor, int N, int E, int nb) {
    __shared__ int sh[NB_MAX];
    int t = threadIdx.x;
    if (t < NB_MAX) sh[t] = (t < nb) ? blocksums[t] : 0;
    __syncthreads();
    for (int off = 1; off < NB_MAX; off <<= 1) {
        int v = (t < NB_MAX && t >= off) ? sh[t - off] : 0;
        __syncthreads();
        if (t < NB_MAX) sh[t] += v;
        __syncthreads();
    }
    int i = blockIdx.x * blockDim.x + t;
    if (i < N) {
        int r = i / SCAN_B;
        int pre = (r == 0) ? 0 : sh[r - 1];
        int o = offs[i] + pre;
        offs[i] = o;
        cursor[i] = o;
    }
    if (i == 0) offs[N] = E;
}

__global__ void binfill_kernel(const int* __restrict__ src, const int* __restrict__ dst,
                               int* __restrict__ cursor, int* __restrict__ csr_src, int E) {
    int e = blockIdx.x * blockDim.x + threadIdx.x;
    if (e < E) {
        int d = dst[e];
        int p = atomicAdd(&cursor[d], 1);
        csr_src[p] = src[e];
    }
}

__global__ void binfill4_kernel(const int* __restrict__ src, const int* __restrict__ dst,
                                int* __restrict__ cursor, int* __restrict__ csr_src, int E) {
    int e4 = (blockIdx.x * blockDim.x + threadIdx.x) * 4;
    if (e4 >= E) return;
    int4 s = *(const int4*)&src[e4];
    int4 d = *(const int4*)&dst[e4];
    csr_src[atomicAdd(&cursor[d.x], 1)] = s.x;
    csr_src[atomicAdd(&cursor[d.y], 1)] = s.y;
    csr_src[atomicAdd(&cursor[d.z], 1)] = s.z;
    csr_src[atomicAdd(&cursor[d.w], 1)] = s.w;
}

// ---------------------------------------------------------------------------
// Smem-free tensor-core GEMM, MR row-tiles per warp (W fragment amortization):
//   C[N,F](fp16) = (act(A[N,128]) @ W) * dinv[row]
//   Each warp owns MR m16-tiles; per ks the W fragment is loaded once and
//   feeds MR MMAs. A fragments direct from fp32 gmem (fused PRELU).
//   No smem, no __syncthreads. 256 thr / 8 warps.
// ---------------------------------------------------------------------------
template<int F, int CSPLIT, int MR, bool PRELU>
__global__ __launch_bounds__(256)
void gemm_tc_kernel(const float* __restrict__ A, const uint2* __restrict__ fw,
                    const float* __restrict__ biasK, const float* __restrict__ dinv,
                    __half* __restrict__ C, int N) {
    constexpr int K = 128;
    constexpr int NTT = F / 8;
    constexpr int NT = NTT / CSPLIT;
    constexpr int ROWS = (8 / CSPLIT) * 16 * MR;

    const int tid  = threadIdx.x;
    const int warp = tid >> 5;
    const int lane = tid & 31;
    const int g = lane >> 2;
    const int r = lane & 3;
    const int rowgrp = warp / CSPLIT;
    const int colgrp = warp % CSPLIT;
    const int tbase = blockIdx.x * ROWS + rowgrp * 16 * MR;

    int rowA[MR], rowB[MR];
    const float* Aa[MR];
    const float* Ab[MR];
    #pragma unroll
    for (int mr = 0; mr < MR; mr++) {
        rowA[mr] = tbase + mr * 16 + g;
        rowB[mr] = rowA[mr] + 8;
        int ra = (rowA[mr] < N) ? rowA[mr] : N - 1;   // clamp; stores guarded
        int rb = (rowB[mr] < N) ? rowB[mr] : N - 1;
        Aa[mr] = A + (size_t)ra * K;
        Ab[mr] = A + (size_t)rb * K;
    }

    float c[MR][NT][4];
    #pragma unroll
    for (int mr = 0; mr < MR; mr++)
        #pragma unroll
        for (int nt = 0; nt < NT; nt++) {
            c[mr][nt][0] = 0.f; c[mr][nt][1] = 0.f;
            c[mr][nt][2] = 0.f; c[mr][nt][3] = 0.f;
        }

    #pragma unroll
    for (int ks = 0; ks < 8; ks++) {
        const int k0 = ks * 16;
        float2 q0, q1;
        if (PRELU) {
            q0 = *(const float2*)&biasK[k0 + r * 2];
            q1 = *(const float2*)&biasK[k0 + r * 2 + 8];
        }
        uint32_t af[MR][4];
        #pragma unroll
        for (int mr = 0; mr < MR; mr++) {
            float2 va0 = *(const float2*)&Aa[mr][k0 + r * 2];
            float2 va1 = *(const float2*)&Aa[mr][k0 + r * 2 + 8];
            float2 vb0 = *(const float2*)&Ab[mr][k0 + r * 2];
            float2 vb1 = *(const float2*)&Ab[mr][k0 + r * 2 + 8];
            if (PRELU) {
                va0.x = fmaxf(va0.x + q0.x, 0.f); va0.y = fmaxf(va0.y + q0.y, 0.f);
                va1.x = fmaxf(va1.x + q1.x, 0.f); va1.y = fmaxf(va1.y + q1.y, 0.f);
                vb0.x = fmaxf(vb0.x + q0.x, 0.f); vb0.y = fmaxf(vb0.y + q0.y, 0.f);
                vb1.x = fmaxf(vb1.x + q1.x, 0.f); vb1.y = fmaxf(vb1.y + q1.y, 0.f);
            }
            __half2 h0 = __floats2half2_rn(va0.x, va0.y);
            __half2 h1 = __floats2half2_rn(vb0.x, vb0.y);
            __half2 h2 = __floats2half2_rn(va1.x, va1.y);
            __half2 h3 = __floats2half2_rn(vb1.x, vb1.y);
            af[mr][0] = *(uint32_t*)&h0;
            af[mr][1] = *(uint32_t*)&h1;
            af[mr][2] = *(uint32_t*)&h2;
            af[mr][3] = *(uint32_t*)&h3;
        }

        const uint2* fwk = fw + ((size_t)ks * NTT + colgrp * NT) * 32 + lane;
        #pragma unroll
        for (int nt = 0; nt < NT; nt++) {
            uint2 b = __ldg(&fwk[nt * 32]);
            #pragma unroll
            for (int mr = 0; mr < MR; mr++) {
                asm volatile(
                    "mma.sync.aligned.m16n8k16.row.col.f32.f16.f16.f32 "
                    "{%0,%1,%2,%3}, {%4,%5,%6,%7}, {%8,%9}, {%0,%1,%2,%3};"
                    : "+f"(c[mr][nt][0]), "+f"(c[mr][nt][1]),
                      "+f"(c[mr][nt][2]), "+f"(c[mr][nt][3])
                    : "r"(af[mr][0]), "r"(af[mr][1]), "r"(af[mr][2]), "r"(af[mr][3]),
                      "r"(b.x), "r"(b.y));
            }
        }
    }

    const int colbase = colgrp * (F / CSPLIT);
    #pragma unroll
    for (int mr = 0; mr < MR; mr++) {
        const float di0 = (rowA[mr] < N) ? __ldg(&dinv[rowA[mr]]) : 0.f;
        const float di1 = (rowB[mr] < N) ? __ldg(&dinv[rowB[mr]]) : 0.f;
        #pragma unroll
        for (int nt = 0; nt < NT; nt++) {
            int col = colbase + nt * 8 + r * 2;
            if (rowA[mr] < N)
                *(__half2*)&C[(size_t)rowA[mr] * F + col] =
                    __floats2half2_rn(c[mr][nt][0] * di0, c[mr][nt][1] * di0);
            if (rowB[mr] < N)
                *(__half2*)&C[(size_t)rowB[mr] * F + col] =
                    __floats2half2_rn(c[mr][nt][2] * di1, c[mr][nt][3] * di1);
        }
    }
}

// ---------------------------------------------------------------------------
// helpers for fp16 accumulation
// ---------------------------------------------------------------------------
__device__ __forceinline__ void add_h4(float4& acc, uint2 v) {
    __half2 a = *(__half2*)&v.x;
    __half2 b = *(__half2*)&v.y;
    float2 fa = __half22float2(a);
    float2 fb = __half22float2(b);
    acc.x += fa.x; acc.y += fa.y; acc.z += fb.x; acc.w += fb.y;
}

__device__ __forceinline__ void add_h8(float4& acc0, float4& acc1, uint4 v) {
    uint2 lo; lo.x = v.x; lo.y = v.y;
    uint2 hi; hi.x = v.z; hi.y = v.w;
    add_h4(acc0, lo);
    add_h4(acc1, hi);
}

// ---------------------------------------------------------------------------
// CSR gather, layer 1 (F=128, fp16). TWO nodes per warp: 16 lanes/node,
// lane covers 8 halves (uint4 = 16B). Doubles per-warp edge MLP.
// ---------------------------------------------------------------------------
__global__ __launch_bounds__(256)
void gather128h2_kernel(const __half* __restrict__ hn, const int* __restrict__ offs,
                        const int* __restrict__ csr, const float* __restrict__ dinv,
                        float* __restrict__ out, int N) {
    int gid = blockIdx.x * 256 + threadIdx.x;
    int node = gid >> 4;                 // 16 lanes per node
    int l = threadIdx.x & 15;
    if (node >= N) return;
    int beg = __ldg(&offs[node]);
    int end = __ldg(&offs[node + 1]);
    float di = __ldg(&dinv[node]);

    float4 acc0 = make_float4(0.f, 0.f, 0.f, 0.f);
    float4 acc1 = make_float4(0.f, 0.f, 0.f, 0.f);
    add_h8(acc0, acc1, *(const uint4*)(hn + (size_t)node * 128 + l * 8));  // self-loop

    int j = beg;
    for (; j + 3 < end; j += 4) {
        int s0 = __ldg(&csr[j + 0]);
        int s1 = __ldg(&csr[j + 1]);
        int s2 = __ldg(&csr[j + 2]);
        int s3 = __ldg(&csr[j + 3]);
        uint4 v0 = *(const uint4*)(hn + (size_t)s0 * 128 + l * 8);
        uint4 v1 = *(const uint4*)(hn + (size_t)s1 * 128 + l * 8);
        uint4 v2 = *(const uint4*)(hn + (size_t)s2 * 128 + l * 8);
        uint4 v3 = *(const uint4*)(hn + (size_t)s3 * 128 + l * 8);
        add_h8(acc0, acc1, v0); add_h8(acc0, acc1, v1);
        add_h8(acc0, acc1, v2); add_h8(acc0, acc1, v3);
    }
    for (; j < end; j++) {
        int s = __ldg(&csr[j]);
        add_h8(acc0, acc1, *(const uint4*)(hn + (size_t)s * 128 + l * 8));
    }
    acc0.x *= di; acc0.y *= di; acc0.z *= di; acc0.w *= di;
    acc1.x *= di; acc1.y *= di; acc1.z *= di; acc1.w *= di;
    *(float4*)&out[(size_t)node * 128 + l * 8]     = acc0;
    *(float4*)&out[(size_t)node * 128 + l * 8 + 4] = acc1;
}

// ---------------------------------------------------------------------------
// CSR gather, layer 2 (F=64, fp16) + final bias/relu. Two nodes per warp.
// ---------------------------------------------------------------------------
__global__ __launch_bounds__(256)
void gather64h2_kernel(const __half* __restrict__ hn, const int* __restrict__ offs,
                       const int* __restrict__ csr, const float* __restrict__ dinv,
                       const float* __restrict__ b2, float* __restrict__ out, int N) {
    int gid = blockIdx.x * 256 + threadIdx.x;
    int node = gid >> 4;
    int l = threadIdx.x & 15;
    if (node >= N) return;
    int beg = __ldg(&offs[node]);
    int end = __ldg(&offs[node + 1]);
    float di = __ldg(&dinv[node]);

    float4 acc = make_float4(0.f, 0.f, 0.f, 0.f);
    add_h4(acc, *(const uint2*)(hn + (size_t)node * 64 + l * 4));     // self-loop

    int j = beg;
    for (; j + 3 < end; j += 4) {
        int s0 = __ldg(&csr[j + 0]);
        int s1 = __ldg(&csr[j + 1]);
        int s2 = __ldg(&csr[j + 2]);
        int s3 = __ldg(&csr[j + 3]);
        uint2 v0 = *(const uint2*)(hn + (size_t)s0 * 64 + l * 4);
        uint2 v1 = *(const uint2*)(hn + (size_t)s1 * 64 + l * 4);
        uint2 v2 = *(const uint2*)(hn + (size_t)s2 * 64 + l * 4);
        uint2 v3 = *(const uint2*)(hn + (size_t)s3 * 64 + l * 4);
        add_h4(acc, v0); add_h4(acc, v1); add_h4(acc, v2); add_h4(acc, v3);
    }
    for (; j < end; j++) {
        int s = __ldg(&csr[j]);
        add_h4(acc, *(const uint2*)(hn + (size_t)s * 64 + l * 4));
    }
    float4 bb = *(const float4*)&b2[l * 4];
    acc.x = fmaxf(acc.x * di + bb.x, 0.f);
    acc.y = fmaxf(acc.y * di + bb.y, 0.f);
    acc.z = fmaxf(acc.z * di + bb.z, 0.f);
    acc.w = fmaxf(acc.w * di + bb.w, 0.f);
    *(float4*)&out[(size_t)node * 64 + l * 4] = acc;
}

// ---------------------------------------------------------------------------
extern "C" void kernel_launch(void* const* d_in, const int* in_sizes, int n_in,
                              void* d_out, int out_size) {
    const float* x  = (const float*)d_in[0];
    const int*   ei = (const int*)d_in[1];     // int32 (JAX x64 disabled)
    const float* W1 = (const float*)d_in[2];
    const float* b1 = (const float*)d_in[3];
    const float* W2 = (const float*)d_in[4];
    const float* b2 = (const float*)d_in[5];
    float*       out = (float*)d_out;

    const int N = in_sizes[0] / IN_DIM;
    const int E = in_sizes[1] / 2;
    (void)n_in; (void)out_size;

    void* p;
    cudaGetSymbolAddress(&p, g_h);        float* h    = (float*)p;
    cudaGetSymbolAddress(&p, g_agg);      float* agg  = (float*)p;
    cudaGetSymbolAddress(&p, g_dinv);     float* dinv = (float*)p;
    cudaGetSymbolAddress(&p, g_deg);      int*   deg  = (int*)p;
    cudaGetSymbolAddress(&p, g_offs);     int*   offs = (int*)p;
    cudaGetSymbolAddress(&p, g_cursor);   int*   cursor = (int*)p;
    cudaGetSymbolAddress(&p, g_csr_src);  int*   csr  = (int*)p;
    cudaGetSymbolAddress(&p, g_blocksums);int*   bsums = (int*)p;
    cudaGetSymbolAddress(&p, g_fw);       uint2* fw   = (uint2*)p;

    const int* src = ei;
    const int* dst = ei + E;
    const int nb = (N + SCAN_B - 1) / SCAN_B;
    const bool vec4 = (E % 4 == 0);
    const int C1 = 8 * 16 * 32;          // layer-1 fragment words

    // 1-3: init (zero deg + fragment-ordered W), deg histogram, block scan (+dinv)
    init_kernel<<<(N + 255) / 256, 256>>>(W1, W2, fw, deg, N);
    if (vec4) deg4_kernel<<<(E / 4 + 255) / 256, 256>>>(dst, deg, E);
    else      deg_kernel<<<(E + 255) / 256, 256>>>(dst, deg, E);
    scan_block_kernel<<<nb, SCAN_B>>>(deg, offs, bsums, dinv, N);

    // 4: layer-1 GEMM (CSPLIT=2, MR=2: 128 rows/block) — profiled 4th launch
    gemm_tc_kernel<128, 2, 2, false><<<(N + 127) / 128, 256>>>(x, fw, nullptr, dinv, (__half*)h, N);

    // 5-6: finish CSR build
    scan_add_kernel<<<(N + 255) / 256, 256>>>(offs, bsums, cursor, N, E, nb);
    if (vec4) binfill4_kernel<<<(E / 4 + 255) / 256, 256>>>(src, dst, cursor, csr, E);
    else      binfill_kernel<<<(E + 255) / 256, 256>>>(src, dst, cursor, csr, E);

    // 7: layer-1 gather (two nodes per warp)
    gather128h2_kernel<<<(N * 16 + 255) / 256, 256>>>((const __half*)h, offs, csr, dinv, agg, N);

    // 8-9: layer-2 GEMM (CSPLIT=1, MR=2: 256 rows/block, fused relu+b1) + gather
    gemm_tc_kernel<64, 1, 2, true><<<(N + 255) / 256, 256>>>(agg, fw + C1, b1, dinv, (__half*)h, N);
    gather64h2_kernel<<<(N * 16 + 255) / 256, 256>>>((const __half*)h, offs, csr, dinv, b2, out, N);
}